// round 11
// baseline (speedup 1.0000x reference)
#include <cuda_runtime.h>
#include <cuda_fp16.h>
#include <stdint.h>

#define BATCH 4
#define SEQ   8192
#define DIM   64
#define NHASH 8
#define TM    128
#define NTHR  256

// ---------------------------------------------------------------------------
// Device scratch (allowed: __device__ globals)
// ---------------------------------------------------------------------------
__device__ __half g_rotT[2][NHASH][64][64];   // [split][h][i(n)][f(k)]

// ---------------------------------------------------------------------------
// Helpers
// ---------------------------------------------------------------------------
__device__ __forceinline__ uint32_t smem_u32(const void* p) {
    uint32_t a;
    asm("{ .reg .u64 t; cvta.to.shared.u64 t, %1; cvt.u32.u64 %0, t; }" : "=r"(a) : "l"(p));
    return a;
}
#define SWZ(off) ((off) ^ (((off) >> 3) & 0x70))

__device__ __forceinline__ void ldsm_x4(uint32_t* r, uint32_t addr) {
    asm volatile("ldmatrix.sync.aligned.m8n8.x4.shared.b16 {%0,%1,%2,%3}, [%4];"
        : "=r"(r[0]), "=r"(r[1]), "=r"(r[2]), "=r"(r[3]) : "r"(addr));
}
__device__ __forceinline__ void mma_f16(float* d, const uint32_t* a, const uint32_t* b) {
    asm volatile("mma.sync.aligned.m16n8k16.row.col.f32.f16.f16.f32 "
        "{%0,%1,%2,%3}, {%4,%5,%6,%7}, {%8,%9}, {%0,%1,%2,%3};"
        : "+f"(d[0]), "+f"(d[1]), "+f"(d[2]), "+f"(d[3])
        : "r"(a[0]), "r"(a[1]), "r"(a[2]), "r"(a[3]), "r"(b[0]), "r"(b[1]));
}
__device__ __forceinline__ uint32_t pack_h2(__half a, __half b) {
    return (uint32_t)__half_as_ushort(a) | ((uint32_t)__half_as_ushort(b) << 16);
}

// ---------------------------------------------------------------------------
// Prepass: rot fp32 -> 2x fp16 splits, transposed to [i][f] (tiny, runs once)
// ---------------------------------------------------------------------------
__global__ void prepass_rot(const float* __restrict__ rot)   // [f=64][h=8][i=64]
{
    int idx = blockIdx.x * blockDim.x + threadIdx.x;          // 32768
    int f = idx >> 9, rem = idx & 511, h = rem >> 6, i = rem & 63;
    float x = rot[idx];
    __half b0 = __float2half_rn(x);
    float r = x - __half2float(b0);
    __half b1 = __float2half_rn(r);
    g_rotT[0][h][i][f] = b0;
    g_rotT[1][h][i][f] = b1;
}

// ---------------------------------------------------------------------------
// Main kernel: 256 threads / 8 warps, warp owns 16 rows of the 128x64 D tile.
//   A: q fp32 tile split in-block to fp16 (A0 hi, A1 residual), SWZ smem.
//   B: both fp16 rot splits from g_rotT.
//   D = A0*B0^T + A0*B1^T + A1*B0^T  (mma.sync m16n8k16 f16/f32)
//   K-outer loop loads each fragment once per ks; swizzled addresses hoisted
//   (per-ks variation is addr ^ kb, valid since kb bits are disjoint from
//   column bits and below the swizzle source bits).
//   Per-row signed argmax -> bucket. Fused v copy.
// ---------------------------------------------------------------------------
__global__ __launch_bounds__(NTHR, 2) void lsh_hmma_kernel(
    const float4* __restrict__ qk,
    const float4* __restrict__ vin, float4* __restrict__ vout,
    float* __restrict__ out_buckets)
{
    __shared__ __align__(128) unsigned char sA0[16384];       // 128 x 64 fp16, SWZ
    __shared__ __align__(128) unsigned char sA1[16384];       // 128 x 64 fp16, SWZ
    __shared__ __align__(128) unsigned char sB[2 * 8192];     // 2 x (64 x 64 fp16), SWZ

    const int tid  = threadIdx.x;
    const int lane = tid & 31;
    const int w    = tid >> 5;
    const int t0   = blockIdx.x * TM;
    const int h    = blockIdx.y;
    const int b    = blockIdx.z;

    const uint32_t sA0u = smem_u32(sA0);
    const uint32_t sA1u = smem_u32(sA1);
    const uint32_t sBu  = smem_u32(sB);

    // fused v copy: issue load now, store at end
    float4 vr0; int vbase = 0;
    if (vout) {
        int blin = (b * NHASH + h) * gridDim.x + blockIdx.x;
        vbase = blin * NTHR + tid;                 // 2048*256 = 524288 float4
        vr0 = vin[vbase];
    }

    // ---- load both B splits: 64 rows x 128B each, SWZ ----
    #pragma unroll
    for (int s = 0; s < 2; s++) {
        const uint4* src = reinterpret_cast<const uint4*>(&g_rotT[s][h][0][0]);
        #pragma unroll
        for (int it = 0; it < 2; it++) {
            int idx = tid + it * NTHR;             // 512 uint4
            uint32_t off = (uint32_t)idx * 16;
            *reinterpret_cast<uint4*>(sB + s * 8192 + SWZ(off)) = src[idx];
        }
    }

    // ---- load q fp32 tile, split to fp16 in-block ----
    {
        const float4* qsrc = qk + ((size_t)b * SEQ + t0) * (DIM / 4);
        #pragma unroll
        for (int it = 0; it < 8; it++) {
            int idx = tid + it * NTHR;             // 2048 float4
            float4 x = qsrc[idx];
            float xs[4] = {x.x, x.y, x.z, x.w};
            __half h0[4], h1[4];
            #pragma unroll
            for (int e = 0; e < 4; e++) {
                h0[e] = __float2half_rn(xs[e]);
                float r = xs[e] - __half2float(h0[e]);
                h1[e] = __float2half_rn(r);
            }
            uint2 p0 = {pack_h2(h0[0], h0[1]), pack_h2(h0[2], h0[3])};
            uint2 p1 = {pack_h2(h1[0], h1[1]), pack_h2(h1[2], h1[3])};
            uint32_t off = (uint32_t)idx * 8;      // fp16 tile byte offset
            *reinterpret_cast<uint2*>(sA0 + SWZ(off)) = p0;
            *reinterpret_cast<uint2*>(sA1 + SWZ(off)) = p1;
        }
    }
    __syncthreads();

    float acc[8][4];
    #pragma unroll
    for (int j = 0; j < 8; j++)
        #pragma unroll
        for (int e = 0; e < 4; e++) acc[j][e] = 0.0f;

    // hoisted swizzled base addresses (validated fragment mappings, rounds 8-10)
    const uint32_t aRow = (uint32_t)(lane & 15) * 128 + (lane & 16);
    const uint32_t bRow = (uint32_t)((lane & 7) + ((lane & 16) >> 1)) * 128 + ((lane & 8) << 1);
    const uint32_t aAddr0 = sA0u + SWZ((uint32_t)(w * 16) * 128 + aRow);
    const uint32_t aAddr1 = sA1u + SWZ((uint32_t)(w * 16) * 128 + aRow);
    uint32_t bAddr[4];
    #pragma unroll
    for (int jj = 0; jj < 4; jj++)
        bAddr[jj] = sBu + SWZ((uint32_t)(jj * 16) * 128 + bRow);

    #pragma unroll
    for (int ks = 0; ks < 4; ks++) {
        const uint32_t kb = (uint32_t)ks * 32;
        uint32_t afr0[4], afr1[4];
        ldsm_x4(afr0, aAddr0 ^ kb);
        ldsm_x4(afr1, aAddr1 ^ kb);
        uint32_t bfr0[8][2], bfr1[8][2];
        #pragma unroll
        for (int jj = 0; jj < 4; jj++) {
            uint32_t r[4];
            ldsm_x4(r, (bAddr[jj] ^ kb));
            bfr0[2*jj][0] = r[0]; bfr0[2*jj][1] = r[1];
            bfr0[2*jj+1][0] = r[2]; bfr0[2*jj+1][1] = r[3];
            ldsm_x4(r, (bAddr[jj] ^ kb) + 8192);
            bfr1[2*jj][0] = r[0]; bfr1[2*jj][1] = r[1];
            bfr1[2*jj+1][0] = r[2]; bfr1[2*jj+1][1] = r[3];
        }
        #pragma unroll
        for (int j = 0; j < 8; j++) mma_f16(acc[j], afr0, bfr0[j]);
        #pragma unroll
        for (int j = 0; j < 8; j++) mma_f16(acc[j], afr0, bfr1[j]);
        #pragma unroll
        for (int j = 0; j < 8; j++) mma_f16(acc[j], afr1, bfr0[j]);
    }

    // ---- signed argmax per row from D fragments ----
    // m16n8 D mapping: thread holds rows lane>>2 (c0,c1) and +8 (c2,c3),
    // cols 8j + 2*(lane&3) (+1). Tie -> lower index (associative combine).
    const int cq = lane & 3;
    #pragma unroll
    for (int half = 0; half < 2; half++) {
        float bv = -3.4e38f;
        int   bi = 0;
        #pragma unroll
        for (int j = 0; j < 8; j++) {
            #pragma unroll
            for (int e = 0; e < 2; e++) {
                float v = acc[j][half * 2 + e];
                int idx = 8 * j + 2 * cq + e;
                if (v > bv || (v == bv && idx < bi)) { bv = v; bi = idx; }
                float nv = -v; int nidx = idx + 64;
                if (nv > bv || (nv == bv && nidx < bi)) { bv = nv; bi = nidx; }
            }
        }
        #pragma unroll
        for (int m = 1; m < 4; m <<= 1) {
            float ov = __shfl_xor_sync(0xffffffffu, bv, m);
            int   oi = __shfl_xor_sync(0xffffffffu, bi, m);
            if (ov > bv || (ov == bv && oi < bi)) { bv = ov; bi = oi; }
        }
        if (cq == 0) {
            int row = w * 16 + half * 8 + (lane >> 2);
            out_buckets[((size_t)b * NHASH + h) * SEQ + t0 + row] = (float)(bi + h * 128);
        }
    }

    // ---- store fused v copy ----
    if (vout) vout[vbase] = vr0;
}

// ---------------------------------------------------------------------------
// Standalone copy (out-only harness layout)
// ---------------------------------------------------------------------------
__global__ void copy_v_kernel(const float4* __restrict__ v, float4* __restrict__ out, int n4)
{
    int i = blockIdx.x * blockDim.x + threadIdx.x;
    int stride = gridDim.x * blockDim.x;
    for (; i < n4; i += stride) out[i] = v[i];
}

// ---------------------------------------------------------------------------
// Launch
// ---------------------------------------------------------------------------
extern "C" void kernel_launch(void* const* d_in, const int* in_sizes, int n_in,
                              void* d_out, int out_size)
{
    const float* qk  = (const float*)d_in[0];   // (4, 8192, 64)
    const float* v   = (const float*)d_in[1];   // (4, 8192, 64)
    const float* rot = (const float*)d_in[2];   // (1, 64, 8, 64)
    float* out = (float*)d_out;

    const int N_OUT = BATCH * SEQ * DIM;        // 2,097,152
    const int N_BKT = BATCH * NHASH * SEQ;      //   262,144

    if (out_size == N_OUT) {
        copy_v_kernel<<<1024, 256>>>((const float4*)v, (float4*)out, N_OUT / 4);
        return;
    }

    float4* vout  = nullptr;
    float*  out_b = out;
    if (out_size != N_BKT) {                    // combined (default): out || buckets
        vout  = (float4*)out;
        out_b = out + N_OUT;
    }

    prepass_rot<<<128, 256>>>(rot);
    dim3 grid(SEQ / TM, NHASH, BATCH);          // (64, 8, 4) = 2048 blocks
    lsh_hmma_kernel<<<grid, NTHR>>>((const float4*)qk, (const float4*)v, vout, out_b);
}

// round 12
// speedup vs baseline: 1.2606x; 1.2606x over previous
#include <cuda_runtime.h>
#include <cuda_fp16.h>
#include <stdint.h>

#define BATCH 4
#define SEQ   8192
#define DIM   64
#define NHASH 8
#define TM    64
#define NTHR  128

// ---------------------------------------------------------------------------
// Device scratch (allowed: __device__ globals)
// ---------------------------------------------------------------------------
__device__ __half g_rotT[2][NHASH][64][64];   // [split][h][i(n)][f(k)]

// ---------------------------------------------------------------------------
// Helpers
// ---------------------------------------------------------------------------
__device__ __forceinline__ uint32_t smem_u32(const void* p) {
    uint32_t a;
    asm("{ .reg .u64 t; cvta.to.shared.u64 t, %1; cvt.u32.u64 %0, t; }" : "=r"(a) : "l"(p));
    return a;
}
#define SWZ(off) ((off) ^ (((off) >> 3) & 0x70))

__device__ __forceinline__ void ldsm_x4(uint32_t* r, uint32_t addr) {
    asm volatile("ldmatrix.sync.aligned.m8n8.x4.shared.b16 {%0,%1,%2,%3}, [%4];"
        : "=r"(r[0]), "=r"(r[1]), "=r"(r[2]), "=r"(r[3]) : "r"(addr));
}
__device__ __forceinline__ void mma_f16(float* d, const uint32_t* a, const uint32_t* b) {
    asm volatile("mma.sync.aligned.m16n8k16.row.col.f32.f16.f16.f32 "
        "{%0,%1,%2,%3}, {%4,%5,%6,%7}, {%8,%9}, {%0,%1,%2,%3};"
        : "+f"(d[0]), "+f"(d[1]), "+f"(d[2]), "+f"(d[3])
        : "r"(a[0]), "r"(a[1]), "r"(a[2]), "r"(a[3]), "r"(b[0]), "r"(b[1]));
}
__device__ __forceinline__ uint32_t pack_h2(__half a, __half b) {
    return (uint32_t)__half_as_ushort(a) | ((uint32_t)__half_as_ushort(b) << 16);
}
__device__ __forceinline__ void cp_async16(uint32_t dst_smem, const void* src) {
    asm volatile("cp.async.cg.shared.global [%0], [%1], 16;" :: "r"(dst_smem), "l"(src));
}
__device__ __forceinline__ void cp_commit() {
    asm volatile("cp.async.commit_group;" ::: "memory");
}
__device__ __forceinline__ void cp_wait0() {
    asm volatile("cp.async.wait_group 0;" ::: "memory");
}

// ---------------------------------------------------------------------------
// Prepass: rot fp32 -> 2x fp16 splits, transposed to [i][f] (tiny, runs once)
// ---------------------------------------------------------------------------
__global__ void prepass_rot(const float* __restrict__ rot)   // [f=64][h=8][i=64]
{
    int idx = blockIdx.x * blockDim.x + threadIdx.x;          // 32768
    int f = idx >> 9, rem = idx & 511, h = rem >> 6, i = rem & 63;
    float x = rot[idx];
    __half b0 = __float2half_rn(x);
    float r = x - __half2float(b0);
    __half b1 = __float2half_rn(r);
    g_rotT[0][h][i][f] = b0;
    g_rotT[1][h][i][f] = b1;
}

// ---------------------------------------------------------------------------
// Main kernel: block = (b, 64-row t-tile), loops over all 8 hash rounds.
//   q loaded + fp16-split ONCE; A fragments hoisted to registers (ldsm once).
//   B[h] double-buffered in smem via cp.async (prefetch h+1 during h's MMAs).
//   D(64x64) per h = A0*B0^T + A0*B1^T + A1*B0^T (m16n8k16 f16/f32).
//   Argmax via max-|abs| (FMNMX.FABS) + equality/min-index pass; side from
//   sign bit; ties -> positive side / lower index (matches jnp.argmax).
// smem: sB[2][16KB]; A staging overlays sB[1] (dead after frag hoist). 32KB.
// ---------------------------------------------------------------------------
__global__ __launch_bounds__(NTHR) void lsh_hmma_kernel(
    const float4* __restrict__ qk,
    const float4* __restrict__ vin, float4* __restrict__ vout,
    float* __restrict__ out_buckets)
{
    __shared__ __align__(128) unsigned char sB[2][16384];  // per buf: [split0 8K][split1 8K]

    const int tid  = threadIdx.x;
    const int lane = tid & 31;
    const int w    = tid >> 5;
    const int t0   = blockIdx.x * TM;
    const int b    = blockIdx.y;

    const uint32_t sB0u = smem_u32(sB[0]);                 // sB[1] = sB0u + 16384
    unsigned char* sAst = sB[1];                           // A staging overlay

    // ---- prefetch B[0] (both splits, 16KB) via cp.async ----
    #pragma unroll
    for (int it = 0; it < 8; it++) {
        int idx = tid + it * NTHR;                         // 1024 x 16B
        int s = idx >> 9;
        uint32_t o = (uint32_t)(idx & 511) * 16;
        cp_async16(sB0u + s * 8192 + SWZ(o),
                   reinterpret_cast<const char*>(&g_rotT[s][0][0][0]) + o);
    }
    cp_commit();

    // ---- load q fp32 tile (64 rows), split to fp16 into staging ----
    {
        const float4* qsrc = qk + ((size_t)b * SEQ + t0) * (DIM / 4);
        #pragma unroll
        for (int it = 0; it < 8; it++) {
            int idx = tid + it * NTHR;                     // 1024 float4
            float4 x = qsrc[idx];
            float xs[4] = {x.x, x.y, x.z, x.w};
            __half h0[4], h1[4];
            #pragma unroll
            for (int e = 0; e < 4; e++) {
                h0[e] = __float2half_rn(xs[e]);
                float r = xs[e] - __half2float(h0[e]);
                h1[e] = __float2half_rn(r);
            }
            uint2 p0 = {pack_h2(h0[0], h0[1]), pack_h2(h0[2], h0[3])};
            uint2 p1 = {pack_h2(h1[0], h1[1]), pack_h2(h1[2], h1[3])};
            uint32_t off = (uint32_t)idx * 8;
            *reinterpret_cast<uint2*>(sAst + SWZ(off))        = p0;
            *reinterpret_cast<uint2*>(sAst + 8192 + SWZ(off)) = p1;
        }
    }
    __syncthreads();

    // ---- hoist A fragments to registers (once, reused by all 8 h-rounds) ----
    // validated mappings (rounds 8-11); XOR-kb trick valid: row-offset bits 5,6
    // are zero pre-swizzle and kb doesn't feed the swizzle source bits.
    const uint32_t aRow = (uint32_t)(lane & 15) * 128 + (lane & 16);
    const uint32_t aA0  = (sB0u + 16384) + SWZ((uint32_t)(w * 16) * 128 + aRow);
    uint32_t afr0[4][4], afr1[4][4];
    #pragma unroll
    for (int ks = 0; ks < 4; ks++) {
        uint32_t kb = (uint32_t)ks * 32;
        ldsm_x4(afr0[ks], aA0 ^ kb);
        ldsm_x4(afr1[ks], (aA0 + 8192) ^ kb);
    }

    const uint32_t bRow = (uint32_t)((lane & 7) + ((lane & 16) >> 1)) * 128 + ((lane & 8) << 1);
    uint32_t bA[4];
    #pragma unroll
    for (int jj = 0; jj < 4; jj++)
        bA[jj] = SWZ((uint32_t)(jj * 16) * 128 + bRow);

    cp_wait0();
    __syncthreads();   // B[0] visible; all warps done reading A staging

    const int blin = b * gridDim.x + blockIdx.x;           // for v copy
    const int cq   = lane & 3;

    for (int h = 0; h < NHASH; h++) {
        const int cur = h & 1;
        // prefetch next B into the other buffer (reads of it finished at h-1 sync)
        if (h < NHASH - 1) {
            #pragma unroll
            for (int it = 0; it < 8; it++) {
                int idx = tid + it * NTHR;
                int s = idx >> 9;
                uint32_t o = (uint32_t)(idx & 511) * 16;
                cp_async16(sB0u + (1 - cur) * 16384 + s * 8192 + SWZ(o),
                           reinterpret_cast<const char*>(&g_rotT[s][h + 1][0][0]) + o);
            }
            cp_commit();
        }
        // fused v copy slice for this h
        float4 vt;
        if (vout) vt = vin[(size_t)blin * 1024 + h * NTHR + tid];

        float acc[8][4];
        #pragma unroll
        for (int j = 0; j < 8; j++)
            #pragma unroll
            for (int e = 0; e < 4; e++) acc[j][e] = 0.0f;

        const uint32_t bufB = sB0u + cur * 16384;
        #pragma unroll
        for (int ks = 0; ks < 4; ks++) {
            const uint32_t kb = (uint32_t)ks * 32;
            uint32_t bfr0[8][2], bfr1[8][2];
            #pragma unroll
            for (int jj = 0; jj < 4; jj++) {
                uint32_t r[4];
                ldsm_x4(r, bufB + (bA[jj] ^ kb));
                bfr0[2*jj][0] = r[0]; bfr0[2*jj][1] = r[1];
                bfr0[2*jj+1][0] = r[2]; bfr0[2*jj+1][1] = r[3];
                ldsm_x4(r, bufB + 8192 + (bA[jj] ^ kb));
                bfr1[2*jj][0] = r[0]; bfr1[2*jj][1] = r[1];
                bfr1[2*jj+1][0] = r[2]; bfr1[2*jj+1][1] = r[3];
            }
            #pragma unroll
            for (int j = 0; j < 8; j++) mma_f16(acc[j], afr0[ks], bfr0[j]);
            #pragma unroll
            for (int j = 0; j < 8; j++) mma_f16(acc[j], afr0[ks], bfr1[j]);
            #pragma unroll
            for (int j = 0; j < 8; j++) mma_f16(acc[j], afr1[ks], bfr0[j]);
        }

        // ---- signed argmax via max-|abs| ----
        // max over [r, -r] = max|r|; winner side from sign bit; ties ->
        // positive side / lower index (= jnp.argmax first-occurrence).
        #pragma unroll
        for (int half = 0; half < 2; half++) {
            float m = 0.0f;
            #pragma unroll
            for (int j = 0; j < 8; j++) {
                m = fmaxf(m, fabsf(acc[j][half * 2]));
                m = fmaxf(m, fabsf(acc[j][half * 2 + 1]));
            }
            m = fmaxf(m, __shfl_xor_sync(0xffffffffu, m, 1));
            m = fmaxf(m, __shfl_xor_sync(0xffffffffu, m, 2));
            int best = 1 << 30;
            #pragma unroll
            for (int j = 0; j < 8; j++) {
                #pragma unroll
                for (int e = 0; e < 2; e++) {
                    float v = acc[j][half * 2 + e];
                    int idxc = (8 * j + 2 * cq + e) | (int)((__float_as_uint(v) >> 25) & 64u);
                    if (fabsf(v) == m) best = min(best, idxc);
                }
            }
            best = min(best, __shfl_xor_sync(0xffffffffu, best, 1));
            best = min(best, __shfl_xor_sync(0xffffffffu, best, 2));
            if (cq == 0) {
                int row = w * 16 + half * 8 + (lane >> 2);
                out_buckets[((size_t)b * NHASH + h) * SEQ + t0 + row] = (float)(best + h * 128);
            }
        }

        if (vout) vout[(size_t)blin * 1024 + h * NTHR + tid] = vt;

        if (h < NHASH - 1) {
            cp_wait0();        // next B landed
            __syncthreads();   // and everyone done reading current buffer
        }
    }
}

// ---------------------------------------------------------------------------
// Standalone copy (out-only harness layout)
// ---------------------------------------------------------------------------
__global__ void copy_v_kernel(const float4* __restrict__ v, float4* __restrict__ out, int n4)
{
    int i = blockIdx.x * blockDim.x + threadIdx.x;
    int stride = gridDim.x * blockDim.x;
    for (; i < n4; i += stride) out[i] = v[i];
}

// ---------------------------------------------------------------------------
// Launch
// ---------------------------------------------------------------------------
extern "C" void kernel_launch(void* const* d_in, const int* in_sizes, int n_in,
                              void* d_out, int out_size)
{
    const float* qk  = (const float*)d_in[0];   // (4, 8192, 64)
    const float* v   = (const float*)d_in[1];   // (4, 8192, 64)
    const float* rot = (const float*)d_in[2];   // (1, 64, 8, 64)
    float* out = (float*)d_out;

    const int N_OUT = BATCH * SEQ * DIM;        // 2,097,152
    const int N_BKT = BATCH * NHASH * SEQ;      //   262,144

    if (out_size == N_OUT) {
        copy_v_kernel<<<1024, 256>>>((const float4*)v, (float4*)out, N_OUT / 4);
        return;
    }

    float4* vout  = nullptr;
    float*  out_b = out;
    if (out_size != N_BKT) {                    // combined (default): out || buckets
        vout  = (float4*)out;
        out_b = out + N_OUT;
    }

    prepass_rot<<<128, 256>>>(rot);
    dim3 grid(SEQ / TM, BATCH);                 // (128, 4) = 512 blocks, h-loop inside
    lsh_hmma_kernel<<<grid, NTHR>>>((const float4*)qk, (const float4*)v, vout, out_b);
}

// round 13
// speedup vs baseline: 1.4069x; 1.1161x over previous
#include <cuda_runtime.h>
#include <cuda_fp16.h>
#include <stdint.h>

#define BATCH 4
#define SEQ   8192
#define DIM   64
#define NHASH 8
#define TM    64
#define NTHR  128
#define HPB   4      // hash rounds per block (NHASH / gridDim.z)

// ---------------------------------------------------------------------------
// Device scratch (allowed: __device__ globals)
// ---------------------------------------------------------------------------
__device__ __half g_rotT[2][NHASH][64][64];   // [split][h][i(n)][f(k)]

// ---------------------------------------------------------------------------
// Helpers
// ---------------------------------------------------------------------------
__device__ __forceinline__ uint32_t smem_u32(const void* p) {
    uint32_t a;
    asm("{ .reg .u64 t; cvta.to.shared.u64 t, %1; cvt.u32.u64 %0, t; }" : "=r"(a) : "l"(p));
    return a;
}
#define SWZ(off) ((off) ^ (((off) >> 3) & 0x70))

__device__ __forceinline__ void ldsm_x4(uint32_t* r, uint32_t addr) {
    asm volatile("ldmatrix.sync.aligned.m8n8.x4.shared.b16 {%0,%1,%2,%3}, [%4];"
        : "=r"(r[0]), "=r"(r[1]), "=r"(r[2]), "=r"(r[3]) : "r"(addr));
}
__device__ __forceinline__ void mma_f16(float* d, const uint32_t* a, const uint32_t* b) {
    asm volatile("mma.sync.aligned.m16n8k16.row.col.f32.f16.f16.f32 "
        "{%0,%1,%2,%3}, {%4,%5,%6,%7}, {%8,%9}, {%0,%1,%2,%3};"
        : "+f"(d[0]), "+f"(d[1]), "+f"(d[2]), "+f"(d[3])
        : "r"(a[0]), "r"(a[1]), "r"(a[2]), "r"(a[3]), "r"(b[0]), "r"(b[1]));
}
__device__ __forceinline__ uint32_t pack_h2(__half a, __half b) {
    return (uint32_t)__half_as_ushort(a) | ((uint32_t)__half_as_ushort(b) << 16);
}
__device__ __forceinline__ void cp_async16(uint32_t dst_smem, const void* src) {
    asm volatile("cp.async.cg.shared.global [%0], [%1], 16;" :: "r"(dst_smem), "l"(src));
}
__device__ __forceinline__ void cp_commit() {
    asm volatile("cp.async.commit_group;" ::: "memory");
}
__device__ __forceinline__ void cp_wait0() {
    asm volatile("cp.async.wait_group 0;" ::: "memory");
}

// ---------------------------------------------------------------------------
// Prepass: rot fp32 -> 2x fp16 splits, transposed to [i][f] (tiny, runs once)
// ---------------------------------------------------------------------------
__global__ void prepass_rot(const float* __restrict__ rot)   // [f=64][h=8][i=64]
{
    int idx = blockIdx.x * blockDim.x + threadIdx.x;          // 32768
    int f = idx >> 9, rem = idx & 511, h = rem >> 6, i = rem & 63;
    float x = rot[idx];
    __half b0 = __float2half_rn(x);
    float r = x - __half2float(b0);
    __half b1 = __float2half_rn(r);
    g_rotT[0][h][i][f] = b0;
    g_rotT[1][h][i][f] = b1;
}

// ---------------------------------------------------------------------------
// Main kernel: block = (b, 64-row t-tile, hz) handles HPB=4 hash rounds.
//   q loaded + fp16-split ONCE per block; A fragments hoisted to registers.
//   B[h] double-buffered in smem via cp.async (prefetch h+1 during h's MMAs).
//   D(64x64) per h = A0*B0^T + A0*B1^T + A1*B0^T (m16n8k16 f16/f32).
//   Argmax via max-|abs| + equality/min-index pass (exact jnp.argmax semantics).
// smem: sB[2][16KB]; A staging overlays sB[1] (dead after frag hoist). 32KB.
// Grid 1024 blocks -> ~5 blocks/SM resident (reg-capped), ~20 warps/SM.
// ---------------------------------------------------------------------------
__global__ __launch_bounds__(NTHR) void lsh_hmma_kernel(
    const float4* __restrict__ qk,
    const float4* __restrict__ vin, float4* __restrict__ vout,
    float* __restrict__ out_buckets)
{
    __shared__ __align__(128) unsigned char sB[2][16384];  // per buf: [split0 8K][split1 8K]

    const int tid  = threadIdx.x;
    const int lane = tid & 31;
    const int w    = tid >> 5;
    const int t0   = blockIdx.x * TM;
    const int b    = blockIdx.y;
    const int h0   = blockIdx.z * HPB;

    const uint32_t sB0u = smem_u32(sB[0]);                 // sB[1] = sB0u + 16384
    unsigned char* sAst = sB[1];                           // A staging overlay

    // ---- prefetch B[h0] (both splits, 16KB) via cp.async ----
    #pragma unroll
    for (int it = 0; it < 8; it++) {
        int idx = tid + it * NTHR;                         // 1024 x 16B
        int s = idx >> 9;
        uint32_t o = (uint32_t)(idx & 511) * 16;
        cp_async16(sB0u + s * 8192 + SWZ(o),
                   reinterpret_cast<const char*>(&g_rotT[s][h0][0][0]) + o);
    }
    cp_commit();

    // ---- load q fp32 tile (64 rows), split to fp16 into staging ----
    {
        const float4* qsrc = qk + ((size_t)b * SEQ + t0) * (DIM / 4);
        #pragma unroll
        for (int it = 0; it < 8; it++) {
            int idx = tid + it * NTHR;                     // 1024 float4
            float4 x = qsrc[idx];
            float xs[4] = {x.x, x.y, x.z, x.w};
            __half h0v[4], h1v[4];
            #pragma unroll
            for (int e = 0; e < 4; e++) {
                h0v[e] = __float2half_rn(xs[e]);
                float r = xs[e] - __half2float(h0v[e]);
                h1v[e] = __float2half_rn(r);
            }
            uint2 p0 = {pack_h2(h0v[0], h0v[1]), pack_h2(h0v[2], h0v[3])};
            uint2 p1 = {pack_h2(h1v[0], h1v[1]), pack_h2(h1v[2], h1v[3])};
            uint32_t off = (uint32_t)idx * 8;
            *reinterpret_cast<uint2*>(sAst + SWZ(off))        = p0;
            *reinterpret_cast<uint2*>(sAst + 8192 + SWZ(off)) = p1;
        }
    }
    __syncthreads();

    // ---- hoist A fragments to registers (reused by all HPB h-rounds) ----
    // validated mappings (rounds 8-12); XOR-kb trick valid: row-offset bits 5,6
    // are zero pre-swizzle and kb doesn't feed the swizzle source bits.
    const uint32_t aRow = (uint32_t)(lane & 15) * 128 + (lane & 16);
    const uint32_t aA0  = (sB0u + 16384) + SWZ((uint32_t)(w * 16) * 128 + aRow);
    uint32_t afr0[4][4], afr1[4][4];
    #pragma unroll
    for (int ks = 0; ks < 4; ks++) {
        uint32_t kb = (uint32_t)ks * 32;
        ldsm_x4(afr0[ks], aA0 ^ kb);
        ldsm_x4(afr1[ks], (aA0 + 8192) ^ kb);
    }

    const uint32_t bRow = (uint32_t)((lane & 7) + ((lane & 16) >> 1)) * 128 + ((lane & 8) << 1);
    uint32_t bA[4];
    #pragma unroll
    for (int jj = 0; jj < 4; jj++)
        bA[jj] = SWZ((uint32_t)(jj * 16) * 128 + bRow);

    cp_wait0();
    __syncthreads();   // B[h0] visible; all warps done reading A staging

    const int blin = (b * (int)gridDim.z + blockIdx.z) * (int)gridDim.x + blockIdx.x;
    const int cq   = lane & 3;

    #pragma unroll
    for (int hi = 0; hi < HPB; hi++) {
        const int h   = h0 + hi;
        const int cur = hi & 1;
        // prefetch next B into the other buffer
        if (hi < HPB - 1) {
            #pragma unroll
            for (int it = 0; it < 8; it++) {
                int idx = tid + it * NTHR;
                int s = idx >> 9;
                uint32_t o = (uint32_t)(idx & 511) * 16;
                cp_async16(sB0u + (1 - cur) * 16384 + s * 8192 + SWZ(o),
                           reinterpret_cast<const char*>(&g_rotT[s][h + 1][0][0]) + o);
            }
            cp_commit();
        }
        // fused v copy slice for this hi
        float4 vt;
        if (vout) vt = vin[(size_t)blin * (HPB * NTHR) + hi * NTHR + tid];

        float acc[8][4];
        #pragma unroll
        for (int j = 0; j < 8; j++)
            #pragma unroll
            for (int e = 0; e < 4; e++) acc[j][e] = 0.0f;

        const uint32_t bufB = sB0u + cur * 16384;
        #pragma unroll
        for (int ks = 0; ks < 4; ks++) {
            const uint32_t kb = (uint32_t)ks * 32;
            uint32_t bfr0[8][2], bfr1[8][2];
            #pragma unroll
            for (int jj = 0; jj < 4; jj++) {
                uint32_t r[4];
                ldsm_x4(r, bufB + (bA[jj] ^ kb));
                bfr0[2*jj][0] = r[0]; bfr0[2*jj][1] = r[1];
                bfr0[2*jj+1][0] = r[2]; bfr0[2*jj+1][1] = r[3];
                ldsm_x4(r, bufB + 8192 + (bA[jj] ^ kb));
                bfr1[2*jj][0] = r[0]; bfr1[2*jj][1] = r[1];
                bfr1[2*jj+1][0] = r[2]; bfr1[2*jj+1][1] = r[3];
            }
            #pragma unroll
            for (int j = 0; j < 8; j++) mma_f16(acc[j], afr0[ks], bfr0[j]);
            #pragma unroll
            for (int j = 0; j < 8; j++) mma_f16(acc[j], afr0[ks], bfr1[j]);
            #pragma unroll
            for (int j = 0; j < 8; j++) mma_f16(acc[j], afr1[ks], bfr0[j]);
        }

        // ---- signed argmax via max-|abs| ----
        // max over [r, -r] = max|r|; side from sign bit; ties -> positive side /
        // lower index (= jnp.argmax first-occurrence).
        #pragma unroll
        for (int half = 0; half < 2; half++) {
            float m = 0.0f;
            #pragma unroll
            for (int j = 0; j < 8; j++) {
                m = fmaxf(m, fabsf(acc[j][half * 2]));
                m = fmaxf(m, fabsf(acc[j][half * 2 + 1]));
            }
            m = fmaxf(m, __shfl_xor_sync(0xffffffffu, m, 1));
            m = fmaxf(m, __shfl_xor_sync(0xffffffffu, m, 2));
            int best = 1 << 30;
            #pragma unroll
            for (int j = 0; j < 8; j++) {
                #pragma unroll
                for (int e = 0; e < 2; e++) {
                    float v = acc[j][half * 2 + e];
                    int idxc = (8 * j + 2 * cq + e) | (int)((__float_as_uint(v) >> 25) & 64u);
                    if (fabsf(v) == m) best = min(best, idxc);
                }
            }
            best = min(best, __shfl_xor_sync(0xffffffffu, best, 1));
            best = min(best, __shfl_xor_sync(0xffffffffu, best, 2));
            if (cq == 0) {
                int row = w * 16 + half * 8 + (lane >> 2);
                out_buckets[((size_t)b * NHASH + h) * SEQ + t0 + row] = (float)(best + h * 128);
            }
        }

        if (vout) vout[(size_t)blin * (HPB * NTHR) + hi * NTHR + tid] = vt;

        if (hi < HPB - 1) {
            cp_wait0();        // next B landed
            __syncthreads();   // and everyone done reading current buffer
        }
    }
}

// ---------------------------------------------------------------------------
// Standalone copy (out-only harness layout)
// ---------------------------------------------------------------------------
__global__ void copy_v_kernel(const float4* __restrict__ v, float4* __restrict__ out, int n4)
{
    int i = blockIdx.x * blockDim.x + threadIdx.x;
    int stride = gridDim.x * blockDim.x;
    for (; i < n4; i += stride) out[i] = v[i];
}

// ---------------------------------------------------------------------------
// Launch
// ---------------------------------------------------------------------------
extern "C" void kernel_launch(void* const* d_in, const int* in_sizes, int n_in,
                              void* d_out, int out_size)
{
    const float* qk  = (const float*)d_in[0];   // (4, 8192, 64)
    const float* v   = (const float*)d_in[1];   // (4, 8192, 64)
    const float* rot = (const float*)d_in[2];   // (1, 64, 8, 64)
    float* out = (float*)d_out;

    const int N_OUT = BATCH * SEQ * DIM;        // 2,097,152
    const int N_BKT = BATCH * NHASH * SEQ;      //   262,144

    if (out_size == N_OUT) {
        copy_v_kernel<<<1024, 256>>>((const float4*)v, (float4*)out, N_OUT / 4);
        return;
    }

    float4* vout  = nullptr;
    float*  out_b = out;
    if (out_size != N_BKT) {                    // combined (default): out || buckets
        vout  = (float4*)out;
        out_b = out + N_OUT;
    }

    prepass_rot<<<128, 256>>>(rot);
    dim3 grid(SEQ / TM, BATCH, NHASH / HPB);    // (128, 4, 2) = 1024 blocks
    lsh_hmma_kernel<<<grid, NTHR>>>((const float4*)qk, (const float4*)v, vout, out_b);
}

// round 14
// speedup vs baseline: 1.4087x; 1.0013x over previous
#include <cuda_runtime.h>
#include <cuda_fp16.h>
#include <stdint.h>

#define BATCH 4
#define SEQ   8192
#define DIM   64
#define NHASH 8
#define TM    64
#define NTHR  128
#define HPB   4      // hash rounds per block (NHASH / gridDim.z)

// ---------------------------------------------------------------------------
// Device scratch (allowed: __device__ globals)
// ---------------------------------------------------------------------------
__device__ __half g_rotT[2][NHASH][64][64];   // [split][h][i(n)][f(k)]

// ---------------------------------------------------------------------------
// Helpers
// ---------------------------------------------------------------------------
__device__ __forceinline__ uint32_t smem_u32(const void* p) {
    uint32_t a;
    asm("{ .reg .u64 t; cvta.to.shared.u64 t, %1; cvt.u32.u64 %0, t; }" : "=r"(a) : "l"(p));
    return a;
}
#define SWZ(off) ((off) ^ (((off) >> 3) & 0x70))

__device__ __forceinline__ void ldsm_x4(uint32_t* r, uint32_t addr) {
    asm volatile("ldmatrix.sync.aligned.m8n8.x4.shared.b16 {%0,%1,%2,%3}, [%4];"
        : "=r"(r[0]), "=r"(r[1]), "=r"(r[2]), "=r"(r[3]) : "r"(addr));
}
__device__ __forceinline__ void mma_f16(float* d, const uint32_t* a, const uint32_t* b) {
    asm volatile("mma.sync.aligned.m16n8k16.row.col.f32.f16.f16.f32 "
        "{%0,%1,%2,%3}, {%4,%5,%6,%7}, {%8,%9}, {%0,%1,%2,%3};"
        : "+f"(d[0]), "+f"(d[1]), "+f"(d[2]), "+f"(d[3])
        : "r"(a[0]), "r"(a[1]), "r"(a[2]), "r"(a[3]), "r"(b[0]), "r"(b[1]));
}
__device__ __forceinline__ uint32_t pack_h2(__half a, __half b) {
    return (uint32_t)__half_as_ushort(a) | ((uint32_t)__half_as_ushort(b) << 16);
}
__device__ __forceinline__ void cp_async16(uint32_t dst_smem, const void* src) {
    asm volatile("cp.async.cg.shared.global [%0], [%1], 16;" :: "r"(dst_smem), "l"(src));
}
__device__ __forceinline__ void cp_commit() {
    asm volatile("cp.async.commit_group;" ::: "memory");
}
__device__ __forceinline__ void cp_wait0() {
    asm volatile("cp.async.wait_group 0;" ::: "memory");
}

// ---------------------------------------------------------------------------
// Prepass: rot fp32 -> 2x fp16 splits, transposed to [i][f] (tiny, runs once)
// ---------------------------------------------------------------------------
__global__ void prepass_rot(const float* __restrict__ rot)   // [f=64][h=8][i=64]
{
    int idx = blockIdx.x * blockDim.x + threadIdx.x;          // 32768
    int f = idx >> 9, rem = idx & 511, h = rem >> 6, i = rem & 63;
    float x = rot[idx];
    __half b0 = __float2half_rn(x);
    float r = x - __half2float(b0);
    __half b1 = __float2half_rn(r);
    g_rotT[0][h][i][f] = b0;
    g_rotT[1][h][i][f] = b1;
}

// ---------------------------------------------------------------------------
// Main kernel: block = (b, 64-row t-tile, hz) handles HPB=4 hash rounds.
//   q loaded + fp16-split ONCE; A0 fragments hoisted to 16 regs; A1 stays in
//   its own 8KB smem region and is re-ldsm'd per ks (cheap) to cut registers.
//   B[h] double-buffered via cp.async. Inner loop keeps ONE bfr set live:
//     ldsm B0 -> mma A0B0, mma A1B0 -> ldsm B1 (same regs) -> mma A0B1.
//   Argmax via max-|abs| + equality/min-index (exact jnp.argmax semantics).
// smem: sB[2][16KB] (A0 staging overlays sB[1]) + sA1 8KB = 40KB.
// launch_bounds(128,5): ~100-reg cap -> 5 blocks/SM = 20 warps/SM.
// ---------------------------------------------------------------------------
__global__ __launch_bounds__(NTHR, 5) void lsh_hmma_kernel(
    const float4* __restrict__ qk,
    const float4* __restrict__ vin, float4* __restrict__ vout,
    float* __restrict__ out_buckets)
{
    __shared__ __align__(128) unsigned char sB[2][16384];  // per buf: [split0 8K][split1 8K]
    __shared__ __align__(128) unsigned char sA1[8192];     // A residual split, persistent

    const int tid  = threadIdx.x;
    const int lane = tid & 31;
    const int w    = tid >> 5;
    const int t0   = blockIdx.x * TM;
    const int b    = blockIdx.y;
    const int h0   = blockIdx.z * HPB;

    const uint32_t sB0u = smem_u32(sB[0]);                 // sB[1] = sB0u + 16384
    const uint32_t sA1u = smem_u32(sA1);
    unsigned char* sA0st = sB[1];                          // A0 staging overlay (8KB)

    // ---- prefetch B[h0] (both splits, 16KB) via cp.async ----
    #pragma unroll
    for (int it = 0; it < 8; it++) {
        int idx = tid + it * NTHR;                         // 1024 x 16B
        int s = idx >> 9;
        uint32_t o = (uint32_t)(idx & 511) * 16;
        cp_async16(sB0u + s * 8192 + SWZ(o),
                   reinterpret_cast<const char*>(&g_rotT[s][h0][0][0]) + o);
    }
    cp_commit();

    // ---- load q fp32 tile (64 rows), split: A0 -> staging, A1 -> sA1 ----
    {
        const float4* qsrc = qk + ((size_t)b * SEQ + t0) * (DIM / 4);
        #pragma unroll
        for (int it = 0; it < 8; it++) {
            int idx = tid + it * NTHR;                     // 1024 float4
            float4 x = qsrc[idx];
            float xs[4] = {x.x, x.y, x.z, x.w};
            __half h0v[4], h1v[4];
            #pragma unroll
            for (int e = 0; e < 4; e++) {
                h0v[e] = __float2half_rn(xs[e]);
                float r = xs[e] - __half2float(h0v[e]);
                h1v[e] = __float2half_rn(r);
            }
            uint2 p0 = {pack_h2(h0v[0], h0v[1]), pack_h2(h0v[2], h0v[3])};
            uint2 p1 = {pack_h2(h1v[0], h1v[1]), pack_h2(h1v[2], h1v[3])};
            uint32_t off = (uint32_t)idx * 8;
            *reinterpret_cast<uint2*>(sA0st + SWZ(off)) = p0;
            *reinterpret_cast<uint2*>(sA1   + SWZ(off)) = p1;
        }
    }
    __syncthreads();

    // ---- hoist A0 fragments (16 regs); A1 stays in smem ----
    // validated mappings (rounds 8-13); XOR-kb trick valid (kb bits 5-6 are
    // zero pre-swizzle in the row offset and don't feed SWZ source bits 7-9).
    const uint32_t aRow = (uint32_t)(lane & 15) * 128 + (lane & 16);
    const uint32_t aOff = SWZ((uint32_t)(w * 16) * 128 + aRow);
    uint32_t afr0[4][4];
    #pragma unroll
    for (int ks = 0; ks < 4; ks++)
        ldsm_x4(afr0[ks], (sB0u + 16384 + aOff) ^ ((uint32_t)ks * 32));
    const uint32_t aA1 = sA1u + aOff;

    const uint32_t bRow = (uint32_t)((lane & 7) + ((lane & 16) >> 1)) * 128 + ((lane & 8) << 1);
    const uint32_t bOff = SWZ(bRow);   // jj advance = +2048 (commutes with SWZ)

    cp_wait0();
    __syncthreads();   // B[h0] visible; all warps done reading A0 staging

    const int blin = (b * (int)gridDim.z + blockIdx.z) * (int)gridDim.x + blockIdx.x;
    const int cq   = lane & 3;

    #pragma unroll
    for (int hi = 0; hi < HPB; hi++) {
        const int h   = h0 + hi;
        const int cur = hi & 1;
        // prefetch next B into the other buffer
        if (hi < HPB - 1) {
            #pragma unroll
            for (int it = 0; it < 8; it++) {
                int idx = tid + it * NTHR;
                int s = idx >> 9;
                uint32_t o = (uint32_t)(idx & 511) * 16;
                cp_async16(sB0u + (1 - cur) * 16384 + s * 8192 + SWZ(o),
                           reinterpret_cast<const char*>(&g_rotT[s][h + 1][0][0]) + o);
            }
            cp_commit();
        }
        // fused v copy slice for this hi
        float4 vt;
        if (vout) vt = vin[(size_t)blin * (HPB * NTHR) + hi * NTHR + tid];

        float acc[8][4];
        #pragma unroll
        for (int j = 0; j < 8; j++)
            #pragma unroll
            for (int e = 0; e < 4; e++) acc[j][e] = 0.0f;

        const uint32_t bufB = sB0u + cur * 16384;
        #pragma unroll
        for (int ks = 0; ks < 4; ks++) {
            const uint32_t kb = (uint32_t)ks * 32;
            uint32_t afr1[4];
            ldsm_x4(afr1, aA1 ^ kb);
            uint32_t bfr[8][2];
            // B split 0
            #pragma unroll
            for (int jj = 0; jj < 4; jj++) {
                uint32_t r[4];
                ldsm_x4(r, bufB + ((bOff ^ kb) + (uint32_t)jj * 2048));
                bfr[2*jj][0] = r[0]; bfr[2*jj][1] = r[1];
                bfr[2*jj+1][0] = r[2]; bfr[2*jj+1][1] = r[3];
            }
            #pragma unroll
            for (int j = 0; j < 8; j++) mma_f16(acc[j], afr0[ks], bfr[j]);
            #pragma unroll
            for (int j = 0; j < 8; j++) mma_f16(acc[j], afr1, bfr[j]);
            // B split 1 (reuse bfr registers)
            #pragma unroll
            for (int jj = 0; jj < 4; jj++) {
                uint32_t r[4];
                ldsm_x4(r, bufB + 8192 + ((bOff ^ kb) + (uint32_t)jj * 2048));
                bfr[2*jj][0] = r[0]; bfr[2*jj][1] = r[1];
                bfr[2*jj+1][0] = r[2]; bfr[2*jj+1][1] = r[3];
            }
            #pragma unroll
            for (int j = 0; j < 8; j++) mma_f16(acc[j], afr0[ks], bfr[j]);
        }

        // ---- signed argmax via max-|abs| ----
        // max over [r, -r] = max|r|; side from sign bit; ties -> positive side /
        // lower index (= jnp.argmax first-occurrence).
        #pragma unroll
        for (int half = 0; half < 2; half++) {
            float m = 0.0f;
            #pragma unroll
            for (int j = 0; j < 8; j++) {
                m = fmaxf(m, fabsf(acc[j][half * 2]));
                m = fmaxf(m, fabsf(acc[j][half * 2 + 1]));
            }
            m = fmaxf(m, __shfl_xor_sync(0xffffffffu, m, 1));
            m = fmaxf(m, __shfl_xor_sync(0xffffffffu, m, 2));
            int best = 1 << 30;
            #pragma unroll
            for (int j = 0; j < 8; j++) {
                #pragma unroll
                for (int e = 0; e < 2; e++) {
                    float v = acc[j][half * 2 + e];
                    int idxc = (8 * j + 2 * cq + e) | (int)((__float_as_uint(v) >> 25) & 64u);
                    if (fabsf(v) == m) best = min(best, idxc);
                }
            }
            best = min(best, __shfl_xor_sync(0xffffffffu, best, 1));
            best = min(best, __shfl_xor_sync(0xffffffffu, best, 2));
            if (cq == 0) {
                int row = w * 16 + half * 8 + (lane >> 2);
                out_buckets[((size_t)b * NHASH + h) * SEQ + t0 + row] = (float)(best + h * 128);
            }
        }

        if (vout) vout[(size_t)blin * (HPB * NTHR) + hi * NTHR + tid] = vt;

        if (hi < HPB - 1) {
            cp_wait0();        // next B landed
            __syncthreads();   // and everyone done reading current buffer
        }
    }
}

// ---------------------------------------------------------------------------
// Standalone copy (out-only harness layout)
// ---------------------------------------------------------------------------
__global__ void copy_v_kernel(const float4* __restrict__ v, float4* __restrict__ out, int n4)
{
    int i = blockIdx.x * blockDim.x + threadIdx.x;
    int stride = gridDim.x * blockDim.x;
    for (; i < n4; i += stride) out[i] = v[i];
}

// ---------------------------------------------------------------------------
// Launch
// ---------------------------------------------------------------------------
extern "C" void kernel_launch(void* const* d_in, const int* in_sizes, int n_in,
                              void* d_out, int out_size)
{
    const float* qk  = (const float*)d_in[0];   // (4, 8192, 64)
    const float* v   = (const float*)d_in[1];   // (4, 8192, 64)
    const float* rot = (const float*)d_in[2];   // (1, 64, 8, 64)
    float* out = (float*)d_out;

    const int N_OUT = BATCH * SEQ * DIM;        // 2,097,152
    const int N_BKT = BATCH * NHASH * SEQ;      //   262,144

    if (out_size == N_OUT) {
        copy_v_kernel<<<1024, 256>>>((const float4*)v, (float4*)out, N_OUT / 4);
        return;
    }

    float4* vout  = nullptr;
    float*  out_b = out;
    if (out_size != N_BKT) {                    // combined (default): out || buckets
        vout  = (float4*)out;
        out_b = out + N_OUT;
    }

    prepass_rot<<<128, 256>>>(rot);
    dim3 grid(SEQ / TM, BATCH, NHASH / HPB);    // (128, 4, 2) = 1024 blocks
    lsh_hmma_kernel<<<grid, NTHR>>>((const float4*)qk, (const float4*)v, vout, out_b);
}